// round 4
// baseline (speedup 1.0000x reference)
#include <cuda_runtime.h>

// TemporalAttention: B=2, M=16, C=256, H=W=64 (HW=4096), T=1024
// out[b,o,p] = sum_c Wv[o,c] * ( sum_m softmax_m(scale * qk[b]·x[b,m,:,p]) * x[b,m,c,p] ) + bv[o]
// where qk[b] = Wk^T (Wq t[b] + bq), scale = C^-0.5 = 1/16.
// (bk cancels in the softmax; bv hoists out of the softmax-weighted sum since sum_m p_m = 1.)

#define BDIM 256
#define CC   256
#define HWP  4096
#define MMAPS 16
#define TDIM 1024
#define PTILE 32

// dynamic smem layout (floats):
//   qk    [0, 256)
//   spart [256, 256+8*33)
//   ysm   [1024, 1024+256*36)      (c-major, pixel stride 1, row stride 36)
//   Wvs   [10240, 10240+256*65)    (Wv chunk [o][cl], stride 65)
#define SMEM_FLOATS (10240 + 256*65)
#define SMEM_BYTES  (SMEM_FLOATS * 4)

__device__ float g_qk[2 * CC];

// ---------------- packed f32x2 helpers ----------------
__device__ __forceinline__ unsigned long long pk2(float x, float y) {
    unsigned long long r;
    asm("mov.b64 %0, {%1, %2};" : "=l"(r) : "f"(x), "f"(y));
    return r;
}
__device__ __forceinline__ void upk2(unsigned long long v, float& x, float& y) {
    asm("mov.b64 {%0, %1}, %2;" : "=f"(x), "=f"(y) : "l"(v));
}
__device__ __forceinline__ void fma2(unsigned long long& acc,
                                     unsigned long long a, unsigned long long b) {
    asm("fma.rn.f32x2 %0, %1, %2, %0;" : "+l"(acc) : "l"(a), "l"(b));
}

// ---------------- kernel 1: qk = scale * Wk^T (Wq t + bq) ----------------
__global__ void qk_setup(const float* __restrict__ to, const float* __restrict__ Wq,
                         const float* __restrict__ bq, const float* __restrict__ Wk) {
    __shared__ float ts[TDIM];
    __shared__ float qs[CC];
    const int b = blockIdx.x;
    const int tid = threadIdx.x, w = tid >> 5, l = tid & 31;

    for (int i = tid; i < TDIM; i += BDIM) ts[i] = to[b * TDIM + i];
    __syncthreads();

    // each warp computes 4 c's per pass, lanes split t (coalesced Wq reads)
    for (int pass = 0; pass < 8; pass++) {
        const int cb = pass * 32 + w * 4;
        float a0 = 0.f, a1 = 0.f, a2 = 0.f, a3 = 0.f;
        for (int t = l; t < TDIM; t += 32) {
            const float tv = ts[t];
            a0 = fmaf(Wq[(cb + 0) * TDIM + t], tv, a0);
            a1 = fmaf(Wq[(cb + 1) * TDIM + t], tv, a1);
            a2 = fmaf(Wq[(cb + 2) * TDIM + t], tv, a2);
            a3 = fmaf(Wq[(cb + 3) * TDIM + t], tv, a3);
        }
        #pragma unroll
        for (int off = 16; off > 0; off >>= 1) {
            a0 += __shfl_down_sync(0xffffffffu, a0, off);
            a1 += __shfl_down_sync(0xffffffffu, a1, off);
            a2 += __shfl_down_sync(0xffffffffu, a2, off);
            a3 += __shfl_down_sync(0xffffffffu, a3, off);
        }
        if (l == 0) {
            qs[cb + 0] = a0 + bq[cb + 0];
            qs[cb + 1] = a1 + bq[cb + 1];
            qs[cb + 2] = a2 + bq[cb + 2];
            qs[cb + 3] = a3 + bq[cb + 3];
        }
    }
    __syncthreads();

    // qk[c'] = sum_c q[c] * Wk[c, c'] ; coalesced over c'
    const int cp = tid;
    float acc = 0.f;
    for (int c = 0; c < CC; c++) acc = fmaf(qs[c], Wk[c * CC + cp], acc);
    g_qk[b * CC + cp] = acc * 0.0625f;  // * C^-0.5
}

// ---------------- kernel 2: fused online-softmax + Wv GEMM ----------------
__global__ void __launch_bounds__(BDIM, 2)
attn_kernel(const float* __restrict__ res, const float* __restrict__ Wv,
            const float* __restrict__ bv, float* __restrict__ out) {
    extern __shared__ float sm[];
    float* qk    = sm;                 // 256
    float* spart = sm + 256;           // 8 x 33
    float* ysm   = sm + 1024;          // 256 x 36
    float* Wvs   = sm + 10240;         // 256 x 65

    const int tid = threadIdx.x, w = tid >> 5, l = tid & 31;
    const int b  = blockIdx.x >> 7;            // 128 tiles per batch
    const int p0 = (blockIdx.x & 127) * PTILE;

    if (tid < CC) qk[tid] = g_qk[b * CC + tid];
    __syncthreads();

    // thread owns pixel p = p0 + l, channels c = w + 8k (k=0..31)
    float y[32];
    #pragma unroll
    for (int k = 0; k < 32; k++) y[k] = 0.f;
    float mrun = -1e30f, lrun = 0.f;

    const float* xb0 = res + (size_t)b * MMAPS * CC * HWP + p0 + l;

    for (int m = 0; m < MMAPS; m++) {
        const float* xb = xb0 + (size_t)m * CC * HWP + (size_t)w * HWP;
        float xv[32];
        float s = 0.f;
        #pragma unroll
        for (int k = 0; k < 32; k++) {
            xv[k] = __ldg(xb + (size_t)k * 8 * HWP);   // coalesced 128B per warp
            s = fmaf(qk[w + 8 * k], xv[k], s);
        }
        spart[w * 33 + l] = s;
        __syncthreads();
        float st = 0.f;
        #pragma unroll
        for (int ww = 0; ww < 8; ww++) st += spart[ww * 33 + l];
        __syncthreads();

        const float mnew  = fmaxf(mrun, st);
        const float alpha = __expf(mrun - mnew);
        const float f     = __expf(st - mnew);
        lrun = lrun * alpha + f;
        mrun = mnew;
        #pragma unroll
        for (int k = 0; k < 32; k++) y[k] = fmaf(y[k], alpha, f * xv[k]);
    }

    const float inv = 1.0f / lrun;
    #pragma unroll
    for (int k = 0; k < 32; k++) ysm[(w + 8 * k) * 36 + l] = y[k] * inv;
    __syncthreads();

    // GEMM: out[o, p] = sum_c Wv[o,c] * ysm[c,p] + bv[o]
    // thread -> (og = tid>>3 : 8 o's, pg = tid&7 : 4 p's)
    const int og = tid >> 3, pg = tid & 7;
    unsigned long long acc[8][2];
    #pragma unroll
    for (int i = 0; i < 8; i++) { acc[i][0] = 0ull; acc[i][1] = 0ull; }

    const float4* ysm4 = (const float4*)ysm;   // row stride 9 float4s

    for (int ch = 0; ch < 4; ch++) {
        // stage Wv[:, ch*64 .. ch*64+63] into smem (row-major, stride 65)
        #pragma unroll
        for (int it = 0; it < 16; it++) {
            const int idx = tid + it * BDIM;          // 0..4095 float4s
            const int o = idx >> 4, c4 = idx & 15;
            const float4 v = *(const float4*)(Wv + o * CC + ch * 64 + c4 * 4);
            float* dst = Wvs + o * 65 + c4 * 4;
            dst[0] = v.x; dst[1] = v.y; dst[2] = v.z; dst[3] = v.w;
        }
        __syncthreads();

        #pragma unroll 2
        for (int cl = 0; cl < 64; cl++) {
            const int c = ch * 64 + cl;
            const float4 yv = ysm4[c * 9 + pg];
            const unsigned long long ya = pk2(yv.x, yv.y);
            const unsigned long long yb = pk2(yv.z, yv.w);
            #pragma unroll
            for (int i = 0; i < 8; i++) {
                const float wv = Wvs[(og * 8 + i) * 65 + cl];   // broadcast LDS
                const unsigned long long w2 = pk2(wv, wv);
                fma2(acc[i][0], w2, ya);
                fma2(acc[i][1], w2, yb);
            }
        }
        __syncthreads();
    }

    #pragma unroll
    for (int i = 0; i < 8; i++) {
        const int o = og * 8 + i;
        const float bvo = __ldg(bv + o);
        float x0, x1, x2, x3;
        upk2(acc[i][0], x0, x1);
        upk2(acc[i][1], x2, x3);
        float4 ov = make_float4(x0 + bvo, x1 + bvo, x2 + bvo, x3 + bvo);
        *(float4*)(out + ((size_t)b * CC + o) * HWP + p0 + pg * 4) = ov;
    }
}

extern "C" void kernel_launch(void* const* d_in, const int* in_sizes, int n_in,
                              void* d_out, int out_size) {
    const float* to  = (const float*)d_in[0];  // [B, T]
    const float* res = (const float*)d_in[1];  // [B, M, C, H, W]
    const float* Wq  = (const float*)d_in[2];  // [C, T]
    const float* bq  = (const float*)d_in[3];  // [C]
    // d_in[4] = Wk
    const float* Wk  = (const float*)d_in[4];  // [C, C]
    // d_in[5] = bk : cancels in softmax (uniform shift over m)
    const float* Wv  = (const float*)d_in[6];  // [C, C]
    const float* bv  = (const float*)d_in[7];  // [C]
    float* out = (float*)d_out;                // [B, C, H, W]

    cudaFuncSetAttribute(attn_kernel, cudaFuncAttributeMaxDynamicSharedMemorySize,
                         SMEM_BYTES);

    qk_setup<<<2, BDIM>>>(to, Wq, bq, Wk);
    attn_kernel<<<256, BDIM, SMEM_BYTES>>>(res, Wv, bv, out);
}

// round 5
// speedup vs baseline: 1.6208x; 1.6208x over previous
#include <cuda_runtime.h>

// TemporalAttention: B=2, M=16, C=256, H=W=64 (HW=4096), T=1024
// out[b,o,p] = sum_c Wv[o,c] * ( sum_m softmax_m(scale * qk[b]·x[b,m,:,p]) * x[b,m,c,p] ) + bv[o]
// qk[b] = scale * Wk^T (Wq t[b] + bq); bk cancels in softmax; bv hoists (sum_m p_m = 1).

#define BDIM 256
#define CC   256
#define HWP  4096
#define MMAPS 16
#define TDIM 1024
#define PTILE 32
#define CHW  (CC * HWP)
#define MCHW (MMAPS * CHW)

// attn smem (floats):
//   probs [0, 528)                  probs[m*33 + l]
//   ysm   [544, 544+256*36)         ysm[c*36 + l]  (float4-aligned base)
//   uni   [9760, 9760+8448)         union:
//       score phase: spart[w*528 + m*33 + l] (4224) ; qk at uni+4224 (256)
//       gemm  phase: Wvs[o*33 + cl] (8448)
#define SMEM_FLOATS (9760 + 8448)
#define SMEM_BYTES  (SMEM_FLOATS * 4)

__device__ float g_q [2 * CC];
__device__ float g_qk[2 * CC];

// ---------------- packed f32x2 helpers ----------------
__device__ __forceinline__ unsigned long long pk2(float x, float y) {
    unsigned long long r;
    asm("mov.b64 %0, {%1, %2};" : "=l"(r) : "f"(x), "f"(y));
    return r;
}
__device__ __forceinline__ void upk2(unsigned long long v, float& x, float& y) {
    asm("mov.b64 {%0, %1}, %2;" : "=f"(x), "=f"(y) : "l"(v));
}
__device__ __forceinline__ void fma2(unsigned long long& acc,
                                     unsigned long long a, unsigned long long b) {
    asm("fma.rn.f32x2 %0, %1, %2, %0;" : "+l"(acc) : "l"(a), "l"(b));
}

// ---------------- kernel A: q[b,c] = Wq[c,:]·t[b,:] + bq[c] ----------------
// one warp per (b,c): 512 warps = 64 CTAs x 8 warps
__global__ void q_proj(const float* __restrict__ to, const float* __restrict__ Wq,
                       const float* __restrict__ bq) {
    const int tid = threadIdx.x, w = tid >> 5, l = tid & 31;
    const int gw = blockIdx.x * 8 + w;          // 0..511
    const int b = gw >> 8, c = gw & 255;
    const float* wr = Wq + c * TDIM;
    const float* tr = to + b * TDIM;
    float a = 0.f;
    #pragma unroll 8
    for (int t = l; t < TDIM; t += 32) a = fmaf(__ldg(wr + t), __ldg(tr + t), a);
    #pragma unroll
    for (int off = 16; off > 0; off >>= 1) a += __shfl_down_sync(0xffffffffu, a, off);
    if (l == 0) g_q[b * CC + c] = a + __ldg(bq + c);
}

// ---------------- kernel B: qk[b,cp] = scale * sum_c q[b,c] Wk[c,cp] ----------------
// grid 16: (b, 32-wide cp chunk); threads split c into 8 slices, smem reduce.
__global__ void qk_proj(const float* __restrict__ Wk) {
    __shared__ float qs[CC];
    __shared__ float part[8][33];
    const int tid = threadIdx.x;
    const int b = blockIdx.x >> 3;
    const int cp0 = (blockIdx.x & 7) * 32;
    if (tid < CC) qs[tid] = g_q[b * CC + tid];
    __syncthreads();
    const int cs = tid >> 5, cp = tid & 31;     // c-slice, local cp
    float a = 0.f;
    #pragma unroll 8
    for (int c = cs * 32; c < cs * 32 + 32; c++)
        a = fmaf(qs[c], __ldg(Wk + c * CC + cp0 + cp), a);
    part[cs][cp] = a;
    __syncthreads();
    if (tid < 32) {
        float s = 0.f;
        #pragma unroll
        for (int i = 0; i < 8; i++) s += part[i][tid];
        g_qk[b * CC + cp0 + tid] = s * 0.0625f;   // * C^-0.5
    }
}

// ---------------- kernel C: fused scores + softmax + weighted-sum + Wv GEMM ----------------
__global__ void __launch_bounds__(BDIM, 3)
attn_kernel(const float* __restrict__ res, const float* __restrict__ Wv,
            const float* __restrict__ bv, float* __restrict__ out) {
    extern __shared__ float sm[];
    float* probs = sm;              // 16 x 33
    float* ysm   = sm + 544;        // 256 x 36
    float* uni   = sm + 9760;       // union region
    float* spart = uni;             // 8 x (16 x 33)
    float* qk    = uni + 4224;      // 256
    float* Wvs   = uni;             // 256 x 33 (after score phase)

    const int tid = threadIdx.x, w = tid >> 5, l = tid & 31;
    const int b  = blockIdx.x >> 7;
    const int p0 = (blockIdx.x & 127) * PTILE;

    if (tid < CC) qk[tid] = g_qk[b * CC + tid];
    __syncthreads();

    // thread: pixel p0+l, channels c = w + 8k (k = 0..31)
    const float* xb0 = res + (size_t)b * MCHW + (size_t)w * HWP + p0 + l;

    // ---- score phase: one barrier-free sweep over all (m, k) ----
    float sp[16];
    #pragma unroll
    for (int m = 0; m < MMAPS; m++) sp[m] = 0.f;

    #pragma unroll 4
    for (int k = 0; k < 32; k++) {
        const float qv = qk[w + 8 * k];
        const float* xk = xb0 + (size_t)k * 8 * HWP;
        #pragma unroll
        for (int m = 0; m < MMAPS; m++)
            sp[m] = fmaf(__ldg(xk + (size_t)m * CHW), qv, sp[m]);
    }
    #pragma unroll
    for (int m = 0; m < MMAPS; m++) spart[w * 528 + m * 33 + l] = sp[m];
    __syncthreads();

    // ---- block reduce: 512 (m, pixel) sums, 2 per thread ----
    #pragma unroll
    for (int i = tid; i < 512; i += BDIM) {
        const int m = i >> 5, ll = i & 31;
        float s = 0.f;
        #pragma unroll
        for (int ww = 0; ww < 8; ww++) s += spart[ww * 528 + m * 33 + ll];
        probs[m * 33 + ll] = s;
    }
    __syncthreads();

    // ---- softmax over m, per pixel (warp 0) ----
    if (tid < 32) {
        float mx = -1e30f;
        #pragma unroll
        for (int m = 0; m < MMAPS; m++) mx = fmaxf(mx, probs[m * 33 + tid]);
        float e[16], ssum = 0.f;
        #pragma unroll
        for (int m = 0; m < MMAPS; m++) {
            e[m] = __expf(probs[m * 33 + tid] - mx);
            ssum += e[m];
        }
        const float inv = 1.0f / ssum;
        #pragma unroll
        for (int m = 0; m < MMAPS; m++) probs[m * 33 + tid] = e[m] * inv;
    }
    __syncthreads();

    // ---- y phase: barrier-free weighted sum (re-read tile; mostly L2) ----
    float y[32];
    #pragma unroll
    for (int k = 0; k < 32; k++) y[k] = 0.f;

    for (int m = 0; m < MMAPS; m++) {
        const float f = probs[m * 33 + l];
        const float* xm = xb0 + (size_t)m * CHW;
        #pragma unroll
        for (int k = 0; k < 32; k++)
            y[k] = fmaf(__ldg(xm + (size_t)k * 8 * HWP), f, y[k]);
    }
    #pragma unroll
    for (int k = 0; k < 32; k++) ysm[(w + 8 * k) * 36 + l] = y[k];
    __syncthreads();

    // ---- GEMM: out[o,p] = sum_c Wv[o,c] * ysm[c,p] + bv[o] ----
    // thread -> (og = tid>>3 : 8 o's, pg = tid&7 : 4 p's); c chunked by 32
    const int og = tid >> 3, pg = tid & 7;
    unsigned long long acc[8][2];
    #pragma unroll
    for (int i = 0; i < 8; i++) { acc[i][0] = 0ull; acc[i][1] = 0ull; }

    const float4* ysm4 = (const float4*)ysm;    // row stride 9 float4s

    for (int ch = 0; ch < 8; ch++) {
        // stage Wv[:, ch*32 .. ch*32+31] -> Wvs[o*33 + cl]
        #pragma unroll
        for (int it = 0; it < 8; it++) {
            const int idx = tid + it * BDIM;     // 0..2047 float4s
            const int o = idx >> 3, c4 = idx & 7;
            const float4 v = *(const float4*)(Wv + o * CC + ch * 32 + c4 * 4);
            float* dst = Wvs + o * 33 + c4 * 4;
            dst[0] = v.x; dst[1] = v.y; dst[2] = v.z; dst[3] = v.w;
        }
        __syncthreads();

        #pragma unroll 2
        for (int cl = 0; cl < 32; cl++) {
            const int c = ch * 32 + cl;
            const float4 yv = ysm4[c * 9 + pg];
            const unsigned long long ya = pk2(yv.x, yv.y);
            const unsigned long long yb = pk2(yv.z, yv.w);
            #pragma unroll
            for (int i = 0; i < 8; i++) {
                const float wv = Wvs[(og * 8 + i) * 33 + cl];
                const unsigned long long w2 = pk2(wv, wv);
                fma2(acc[i][0], w2, ya);
                fma2(acc[i][1], w2, yb);
            }
        }
        __syncthreads();
    }

    #pragma unroll
    for (int i = 0; i < 8; i++) {
        const int o = og * 8 + i;
        const float bvo = __ldg(bv + o);
        float x0, x1, x2, x3;
        upk2(acc[i][0], x0, x1);
        upk2(acc[i][1], x2, x3);
        float4 ov = make_float4(x0 + bvo, x1 + bvo, x2 + bvo, x3 + bvo);
        *(float4*)(out + ((size_t)b * CC + o) * HWP + p0 + pg * 4) = ov;
    }
}

extern "C" void kernel_launch(void* const* d_in, const int* in_sizes, int n_in,
                              void* d_out, int out_size) {
    const float* to  = (const float*)d_in[0];  // [B, T]
    const float* res = (const float*)d_in[1];  // [B, M, C, H, W]
    const float* Wq  = (const float*)d_in[2];  // [C, T]
    const float* bq  = (const float*)d_in[3];  // [C]
    const float* Wk  = (const float*)d_in[4];  // [C, C]
    // d_in[5] = bk : cancels in softmax
    const float* Wv  = (const float*)d_in[6];  // [C, C]
    const float* bv  = (const float*)d_in[7];  // [C]
    float* out = (float*)d_out;                // [B, C, H, W]

    cudaFuncSetAttribute(attn_kernel, cudaFuncAttributeMaxDynamicSharedMemorySize,
                         SMEM_BYTES);

    q_proj<<<64, BDIM>>>(to, Wq, bq);
    qk_proj<<<16, BDIM>>>(Wk);
    attn_kernel<<<256, BDIM, SMEM_BYTES>>>(res, Wv, bv, out);
}